// round 1
// baseline (speedup 1.0000x reference)
#include <cuda_runtime.h>
#include <float.h>

#define NB   8
#define NLQ  512
#define NL   4096
#define ND   64
#define TQ   8
#define TK   128
#define KSTR 68          // padded row stride (floats) for k_s / v_s tiles
#define NTHREADS 512

// smem layout (floats)
#define OFF_SC    0                       // TQ*NL      = 32768
#define OFF_KS    (OFF_SC  + TQ*NL)       // TK*KSTR    = 8704
#define OFF_VS    (OFF_KS  + TK*KSTR)     // TK*KSTR    = 8704
#define OFF_MS    (OFF_VS  + TK*KSTR)     // TQ*TK      = 1024
#define OFF_QS    (OFF_MS  + TQ*TK)       // TQ*ND      = 512
#define OFF_MSUM  (OFF_QS  + TQ*ND)       // TQ*ND      = 512
#define OFF_CNT   (OFF_MSUM+ TQ*ND)       // TQ         = 8
#define SMEM_FLOATS (OFF_CNT + TQ)
#define SMEM_BYTES  (SMEM_FLOATS * 4)     // 208,928 B

// mask dtype is ambiguous (numpy bool may arrive as u8 / i32 / f32).
// Detect once per launch, deterministically, on device.
__device__ int g_mask_mode;   // 0 = uint8, 1 = int32, 2 = float32

__global__ void detect_mask_kernel(const unsigned int* __restrict__ m) {
    int allle1 = 1, allf = 1;
    for (int i = 0; i < 32; ++i) {
        unsigned w = m[i];
        if (w > 1u) allle1 = 0;
        if (w != 0u && w != 0x3F800000u) allf = 0;
    }
    g_mask_mode = allf ? 2 : (allle1 ? 1 : 0);
}

__global__ __launch_bounds__(NTHREADS, 1)
void ga_kernel(const float* __restrict__ qg, const float* __restrict__ kg,
               const float* __restrict__ vg, const void* __restrict__ maskg,
               float* __restrict__ out)
{
    extern __shared__ float smem[];
    float* sc   = smem + OFF_SC;
    float* k_s  = smem + OFF_KS;
    float* v_s  = smem + OFF_VS;
    float* m_s  = smem + OFF_MS;
    float* q_s  = smem + OFF_QS;
    float* msum = smem + OFF_MSUM;
    float* cnts = smem + OFF_CNT;

    const int t    = threadIdx.x;
    const int wid  = t >> 5;
    const int lane = t & 31;
    const int b    = blockIdx.x >> 6;          // 64 q-tiles per batch
    const int q0   = (blockIdx.x & 63) * TQ;
    const int mode = g_mask_mode;

    // load Q tile (8 queries x 64 dims)
    q_s[t] = qg[((size_t)b * NLQ + q0) * ND + t];

    // mean-pool accumulators (warps 8..15)
    float4 acc = make_float4(0.f, 0.f, 0.f, 0.f);
    float  cnt = 0.f;
    const int mq   = wid - 8;
    const int half = lane >> 4;
    const int d0   = (lane & 15) * 4;

    const float4* kg4 = (const float4*)(kg + (size_t)b * NL * ND);
    const float4* vg4 = (const float4*)(vg + (size_t)b * NL * ND);

    for (int tile = 0; tile < NL / TK; ++tile) {
        const int l0 = tile * TK;
        __syncthreads();   // previous tile fully consumed

        // ---- load K/V tiles: 2048 float4 each, 4 per thread, pad-68 rows ----
        #pragma unroll
        for (int it = 0; it < 4; ++it) {
            int fid = t + NTHREADS * it;
            int l   = fid >> 4;
            int d4  = fid & 15;
            float4 kv = kg4[(size_t)(l0 + l) * 16 + d4];
            *(float4*)(k_s + l * KSTR + 4 * d4) = kv;
            float4 vv = vg4[(size_t)(l0 + l) * 16 + d4];
            *(float4*)(v_s + l * KSTR + 4 * d4) = vv;
        }
        // ---- mask tile: 8 rows x 128, converted to float ----
        if (t < 256) {
            int qq = t >> 5;
            int li = (t & 31) * 4;
            size_t base = ((size_t)(b * NLQ + q0 + qq)) * NL + l0 + li;
            float4 mv;
            if (mode == 0) {
                uchar4 u = *(const uchar4*)((const unsigned char*)maskg + base);
                mv = make_float4(u.x ? 1.f : 0.f, u.y ? 1.f : 0.f,
                                 u.z ? 1.f : 0.f, u.w ? 1.f : 0.f);
            } else if (mode == 1) {
                int4 u = *(const int4*)((const int*)maskg + base);
                mv = make_float4(u.x ? 1.f : 0.f, u.y ? 1.f : 0.f,
                                 u.z ? 1.f : 0.f, u.w ? 1.f : 0.f);
            } else {
                mv = *(const float4*)((const float*)maskg + base);
            }
            *(float4*)(m_s + qq * TK + li) = mv;
        }
        __syncthreads();

        if (wid < 8) {
            // ---- scores for query `wid` over 128 keys ----
            const int q = wid;
            const float4* q4 = (const float4*)(q_s + q * ND);
            #pragma unroll
            for (int c = 0; c < 4; ++c) {
                int l = 32 * c + lane;
                const float4* kr = (const float4*)(k_s + l * KSTR);
                float s0 = 0.f, s1 = 0.f, s2 = 0.f, s3 = 0.f;
                #pragma unroll
                for (int dd = 0; dd < 16; ++dd) {
                    float4 kk = kr[dd];
                    float4 qq = q4[dd];
                    s0 += qq.x * kk.x; s1 += qq.y * kk.y;
                    s2 += qq.z * kk.z; s3 += qq.w * kk.w;
                }
                float sv = (s0 + s1) + (s2 + s3);
                float m  = m_s[q * TK + l];
                sc[q * NL + l0 + l] = (m != 0.f) ? sv * 0.125f : -FLT_MAX;
            }
        } else {
            // ---- masked mean accumulation for query mq ----
            #pragma unroll 4
            for (int lt = 0; lt < 64; ++lt) {
                int l = 2 * lt + half;
                float  m  = m_s[mq * TK + l];
                float4 vv = *(const float4*)(v_s + l * KSTR + d0);
                acc.x += m * vv.x; acc.y += m * vv.y;
                acc.z += m * vv.z; acc.w += m * vv.w;
                if ((lane & 15) == 0) cnt += m;
            }
        }
    }

    // mean warps: combine the two l-parity halves, publish to smem
    if (wid >= 8) {
        acc.x += __shfl_xor_sync(0xffffffffu, acc.x, 16);
        acc.y += __shfl_xor_sync(0xffffffffu, acc.y, 16);
        acc.z += __shfl_xor_sync(0xffffffffu, acc.z, 16);
        acc.w += __shfl_xor_sync(0xffffffffu, acc.w, 16);
        cnt   += __shfl_xor_sync(0xffffffffu, cnt,   16);
        if (lane < 16) *(float4*)(msum + mq * ND + 4 * lane) = acc;
        if (lane == 0) cnts[mq] = cnt;
    }
    __syncthreads();

    if (wid < 8) {
        const int q = wid;
        const float* row = sc + q * NL;

        // ---- single-scan local top-4 per lane ----
        float v0 = -FLT_MAX, v1 = -FLT_MAX, v2 = -FLT_MAX, v3 = -FLT_MAX;
        int   i0 = NL, i1 = NL, i2 = NL, i3 = NL;
        for (int i = lane; i < NL; i += 32) {
            float x = row[i];
            if (x > v3) {
                if (x > v1) {
                    if (x > v0) { v3=v2;i3=i2; v2=v1;i2=i1; v1=v0;i1=i0; v0=x;i0=i; }
                    else        { v3=v2;i3=i2; v2=v1;i2=i1; v1=x;i1=i; }
                } else {
                    if (x > v2) { v3=v2;i3=i2; v2=x;i2=i; }
                    else        { v3=x;i3=i; }
                }
            }
        }

        // ---- 32-round warp merge: global top-32 ----
        float myval = -FLT_MAX;
        int   myidx = NL;
        for (int s = 0; s < 32; ++s) {
            float cv = v0; int ci = i0;
            #pragma unroll
            for (int off = 16; off; off >>= 1) {
                float ov = __shfl_xor_sync(0xffffffffu, cv, off);
                int   oi = __shfl_xor_sync(0xffffffffu, ci, off);
                if (ov > cv || (ov == cv && oi < ci)) { cv = ov; ci = oi; }
            }
            if (lane == s) { myval = cv; myidx = ci; }
            if (v0 == cv && i0 == ci) {          // I won: pop my head
                v0 = v1; i0 = i1; v1 = v2; i1 = i2; v2 = v3; i2 = i3;
                v3 = -FLT_MAX; i3 = NL;
                if (v0 == -FLT_MAX && cv > -FLT_MAX) {
                    // rare refill: next-best strictly below last popped value
                    float nv = -FLT_MAX; int ni = NL;
                    for (int i = lane; i < NL; i += 32) {
                        float x = row[i];
                        if (x < cv && x > nv) { nv = x; ni = i; }
                    }
                    v0 = nv; i0 = ni;
                }
            }
        }

        // ---- softmax over the 32 selected (lane s holds pick s) ----
        bool  valid = (myval > -1e37f) && (myidx < NL);
        float mmax  = valid ? myval : -FLT_MAX;
        #pragma unroll
        for (int off = 16; off; off >>= 1)
            mmax = fmaxf(mmax, __shfl_xor_sync(0xffffffffu, mmax, off));
        float e  = valid ? __expf(myval - mmax) : 0.f;
        float es = e;
        #pragma unroll
        for (int off = 16; off; off >>= 1)
            es += __shfl_xor_sync(0xffffffffu, es, off);
        float attn = (es > 0.f) ? e / es : 0.f;

        // ---- gather: q_ctx = sum attn_i * v[b, idx_i, :] ----
        const float* vb = vg + (size_t)b * NL * ND;
        float c0 = 0.f, c1 = 0.f;
        #pragma unroll 4
        for (int i = 0; i < 32; ++i) {
            float a   = __shfl_sync(0xffffffffu, attn,  i);
            int   idx = __shfl_sync(0xffffffffu, myidx, i);
            if (a > 0.f && idx < NL) {
                const float* vr = vb + (size_t)idx * ND;
                c0 += a * vr[lane];
                c1 += a * vr[lane + 32];
            }
        }

        // ---- epilogue: mean + q_ctx ----
        float cdiv = fmaxf(cnts[q], 1.f);
        size_t orow = ((size_t)(b * NLQ + q0 + q)) * ND;
        out[orow + lane]      = msum[q * ND + lane]      / cdiv + c0;
        out[orow + lane + 32] = msum[q * ND + lane + 32] / cdiv + c1;
    }
}

extern "C" void kernel_launch(void* const* d_in, const int* in_sizes, int n_in,
                              void* d_out, int out_size) {
    const float* q    = (const float*)d_in[0];
    const float* k    = (const float*)d_in[1];
    const float* v    = (const float*)d_in[2];
    const void*  mask = d_in[3];
    float* out = (float*)d_out;

    cudaFuncSetAttribute(ga_kernel, cudaFuncAttributeMaxDynamicSharedMemorySize,
                         SMEM_BYTES);

    detect_mask_kernel<<<1, 1>>>((const unsigned int*)mask);
    ga_kernel<<<NB * (NLQ / TQ), NTHREADS, SMEM_BYTES>>>(q, k, v, mask, out);
}

// round 2
// speedup vs baseline: 1.6301x; 1.6301x over previous
#include <cuda_runtime.h>
#include <float.h>

typedef unsigned long long ull;

#define NB   8
#define NLQ  512
#define NL   4096
#define ND   64
#define TQ   8
#define TK   128
#define KSTR 68
#define NTHREADS 512
#define NTILES (NL/TK)

// smem layout (floats)
#define OFF_SC    0                        // TQ*NL   = 32768
#define OFF_KS    (OFF_SC  + TQ*NL)        // TK*KSTR = 8704
#define OFF_VS    (OFF_KS  + TK*KSTR)      // TK*KSTR = 8704
#define OFF_MS    (OFF_VS  + TK*KSTR)      // TQ*TK   = 1024
#define OFF_QT    (OFF_MS  + TQ*TK)        // ND*TQ   = 512 (transposed q)
#define OFF_MSUM  (OFF_QT  + ND*TQ)        // TQ*ND   = 512
#define OFF_CNT   (OFF_MSUM+ TQ*ND)        // TQ
#define SMEM_FLOATS (OFF_CNT + TQ)
#define SMEM_BYTES  (SMEM_FLOATS * 4)

// packed fp32x2 ops (sm_103a)
#define F32X2_FMA(d,a,b)  asm("fma.rn.f32x2 %0, %1, %2, %0;" : "+l"(d) : "l"(a), "l"(b))
#define F32X2_ADD(d,a,b)  asm("add.rn.f32x2 %0, %1, %2;"     : "=l"(d) : "l"(a), "l"(b))
#define F32X2_PACK(d,lo,hi)   asm("mov.b64 %0, {%1, %2};" : "=l"(d) : "f"(lo), "f"(hi))
#define F32X2_UNPACK(lo,hi,s) asm("mov.b64 {%0, %1}, %2;" : "=f"(lo), "=f"(hi) : "l"(s))

__device__ int g_mask_mode;   // 0 = uint8, 1 = int32, 2 = float32

__global__ void detect_mask_kernel(const unsigned int* __restrict__ m) {
    int allle1 = 1, allf = 1;
    for (int i = 0; i < 32; ++i) {
        unsigned w = m[i];
        if (w > 1u) allle1 = 0;
        if (w != 0u && w != 0x3F800000u) allf = 0;
    }
    g_mask_mode = allf ? 2 : (allle1 ? 1 : 0);
}

__global__ __launch_bounds__(NTHREADS, 1)
void ga_kernel(const float* __restrict__ qg, const float* __restrict__ kg,
               const float* __restrict__ vg, const void* __restrict__ maskg,
               float* __restrict__ out)
{
    extern __shared__ float smem[];
    float* sc   = smem + OFF_SC;
    float* k_s  = smem + OFF_KS;
    float* v_s  = smem + OFF_VS;
    float* m_s  = smem + OFF_MS;
    float* qT   = smem + OFF_QT;
    float* msum = smem + OFF_MSUM;
    float* cnts = smem + OFF_CNT;

    const int t    = threadIdx.x;
    const int wid  = t >> 5;
    const int lane = t & 31;
    const int b    = blockIdx.x >> 6;
    const int q0   = (blockIdx.x & 63) * TQ;
    const int mode = g_mask_mode;

    // stage Q transposed: qT[d*8+q]
    {
        int d = t >> 3, q = t & 7;
        qT[t] = qg[((size_t)(b * NLQ + q0 + q)) * ND + d];
    }

    const float4* kg4 = (const float4*)(kg + (size_t)b * NL * ND);
    const float4* vg4 = (const float4*)(vg + (size_t)b * NL * ND);

    float4 kr[4], vr[4];
    float4 mv = make_float4(0.f, 0.f, 0.f, 0.f);

    const int fl[4]  = { (t) >> 4, (t + 512) >> 4, (t + 1024) >> 4, (t + 1536) >> 4 };
    const int fd4    = t & 15;
    const int mqq    = t >> 5;          // t<256 only
    const int mli4   = (t & 31) * 4;

    auto LOADT = [&](int tile) {
        const int l0t = tile * TK;
        #pragma unroll
        for (int it = 0; it < 4; ++it) {
            kr[it] = kg4[(size_t)(l0t + fl[it]) * 16 + fd4];
            vr[it] = vg4[(size_t)(l0t + fl[it]) * 16 + fd4];
        }
        if (t < 256) {
            size_t base = ((size_t)(b * NLQ + q0 + mqq)) * NL + l0t + mli4;
            if (mode == 0) {
                uchar4 u = *(const uchar4*)((const unsigned char*)maskg + base);
                mv = make_float4(u.x ? 1.f : 0.f, u.y ? 1.f : 0.f,
                                 u.z ? 1.f : 0.f, u.w ? 1.f : 0.f);
            } else if (mode == 1) {
                int4 u = *(const int4*)((const int*)maskg + base);
                mv = make_float4(u.x ? 1.f : 0.f, u.y ? 1.f : 0.f,
                                 u.z ? 1.f : 0.f, u.w ? 1.f : 0.f);
            } else {
                mv = *(const float4*)((const float*)maskg + base);
            }
        }
    };
    auto STORET = [&]() {
        #pragma unroll
        for (int it = 0; it < 4; ++it) {
            *(float4*)(k_s + fl[it] * KSTR + 4 * fd4) = kr[it];
            *(float4*)(v_s + fl[it] * KSTR + 4 * fd4) = vr[it];
        }
        if (t < 256) *(float4*)(m_s + mqq * TK + mli4) = mv;
    };

    LOADT(0);

    float c0 = 0.f, c1 = 0.f;   // gather result (score warps)

    if (wid < 8) {
        // ================= score path: warp owns 16 keys, all 8 queries ====
        const int li   = lane & 15;
        const int half = lane >> 4;
        const int l    = wid * 16 + li;
        const int db   = half * 32;

        for (int tile = 0; tile < NTILES; ++tile) {
            __syncthreads();
            STORET();
            if (tile + 1 < NTILES) LOADT(tile + 1);
            __syncthreads();

            ull a01 = 0, a23 = 0, a45 = 0, a67 = 0;
            const float* krow = k_s + l * KSTR + db;
            const float* qTd  = qT + db * 8;
            #pragma unroll
            for (int s = 0; s < 8; ++s) {
                float4 k4 = *(const float4*)(krow + 4 * s);
                #pragma unroll
                for (int j = 0; j < 4; ++j) {
                    float kd = (j == 0) ? k4.x : (j == 1) ? k4.y : (j == 2) ? k4.z : k4.w;
                    const float* qrow = qTd + (4 * s + j) * 8;
                    ulonglong2 qA = *(const ulonglong2*)qrow;
                    ulonglong2 qB = *(const ulonglong2*)(qrow + 4);
                    ull kk; F32X2_PACK(kk, kd, kd);
                    F32X2_FMA(a01, kk, qA.x);
                    F32X2_FMA(a23, kk, qA.y);
                    F32X2_FMA(a45, kk, qB.x);
                    F32X2_FMA(a67, kk, qB.y);
                }
            }
            // combine d-halves
            ull o;
            o = __shfl_xor_sync(0xffffffffu, a01, 16); F32X2_ADD(a01, a01, o);
            o = __shfl_xor_sync(0xffffffffu, a23, 16); F32X2_ADD(a23, a23, o);
            o = __shfl_xor_sync(0xffffffffu, a45, 16); F32X2_ADD(a45, a45, o);
            o = __shfl_xor_sync(0xffffffffu, a67, 16); F32X2_ADD(a67, a67, o);

            // lanes<16 write q0..3, lanes>=16 write q4..7
            const int qb = half * 4;
            ull pA = half ? a45 : a01;
            ull pB = half ? a67 : a23;
            float f0, f1, f2, f3;
            F32X2_UNPACK(f0, f1, pA);
            F32X2_UNPACK(f2, f3, pB);
            const int l0 = tile * TK;
            float m0 = m_s[(qb + 0) * TK + l];
            float m1 = m_s[(qb + 1) * TK + l];
            float m2 = m_s[(qb + 2) * TK + l];
            float m3 = m_s[(qb + 3) * TK + l];
            sc[(qb + 0) * NL + l0 + l] = (m0 != 0.f) ? f0 * 0.125f : -FLT_MAX;
            sc[(qb + 1) * NL + l0 + l] = (m1 != 0.f) ? f1 * 0.125f : -FLT_MAX;
            sc[(qb + 2) * NL + l0 + l] = (m2 != 0.f) ? f2 * 0.125f : -FLT_MAX;
            sc[(qb + 3) * NL + l0 + l] = (m3 != 0.f) ? f3 * 0.125f : -FLT_MAX;
        }

        // ================= top-32 + softmax + gather for query q=wid =======
        const int q = wid;
        const float* row = sc + q * NL;

        float v0 = -FLT_MAX, v1 = -FLT_MAX, v2 = -FLT_MAX, v3 = -FLT_MAX;
        int   i0 = NL, i1 = NL, i2 = NL, i3 = NL;
        for (int i = lane; i < NL; i += 32) {
            float x = row[i];
            if (x > v3) {
                if (x > v1) {
                    if (x > v0) { v3=v2;i3=i2; v2=v1;i2=i1; v1=v0;i1=i0; v0=x;i0=i; }
                    else        { v3=v2;i3=i2; v2=v1;i2=i1; v1=x;i1=i; }
                } else {
                    if (x > v2) { v3=v2;i3=i2; v2=x;i2=i; }
                    else        { v3=x;i3=i; }
                }
            }
        }

        float myval = -FLT_MAX;
        int   myidx = NL;
        for (int s = 0; s < 32; ++s) {
            float cv = v0; int ci = i0;
            #pragma unroll
            for (int off = 16; off; off >>= 1) {
                float ov = __shfl_xor_sync(0xffffffffu, cv, off);
                int   oi = __shfl_xor_sync(0xffffffffu, ci, off);
                if (ov > cv || (ov == cv && oi < ci)) { cv = ov; ci = oi; }
            }
            if (lane == s) { myval = cv; myidx = ci; }
            if (v0 == cv && i0 == ci) {
                v0 = v1; i0 = i1; v1 = v2; i1 = i2; v2 = v3; i2 = i3;
                v3 = -FLT_MAX; i3 = NL;
                if (v0 == -FLT_MAX && cv > -FLT_MAX) {
                    float nv = -FLT_MAX; int ni = NL;
                    for (int i = lane; i < NL; i += 32) {
                        float x = row[i];
                        if (x < cv && x > nv) { nv = x; ni = i; }
                    }
                    v0 = nv; i0 = ni;
                }
            }
        }

        bool  valid = (myval > -1e37f) && (myidx < NL);
        float mmax  = valid ? myval : -FLT_MAX;
        #pragma unroll
        for (int off = 16; off; off >>= 1)
            mmax = fmaxf(mmax, __shfl_xor_sync(0xffffffffu, mmax, off));
        float e  = valid ? __expf(myval - mmax) : 0.f;
        float es = e;
        #pragma unroll
        for (int off = 16; off; off >>= 1)
            es += __shfl_xor_sync(0xffffffffu, es, off);
        float attn = (es > 0.f) ? e / es : 0.f;

        const float* vb = vg + (size_t)b * NL * ND;
        #pragma unroll 4
        for (int i = 0; i < 32; ++i) {
            float a   = __shfl_sync(0xffffffffu, attn,  i);
            int   idx = __shfl_sync(0xffffffffu, myidx, i);
            if (a > 0.f && idx < NL) {
                const float* vr2 = vb + (size_t)idx * ND;
                c0 += a * vr2[lane];
                c1 += a * vr2[lane + 32];
            }
        }
        __syncthreads();   // wait for msum/cnts from mean warps
    } else {
        // ================= mean path: warp owns 16 keys ====================
        const int wm    = wid - 8;
        const int c     = lane & 15;
        const int half  = lane >> 4;
        const int lbase = wm * 16;

        ull   accA[8], accB[8];
        float cq[8];
        #pragma unroll
        for (int q = 0; q < 8; ++q) { accA[q] = 0; accB[q] = 0; cq[q] = 0.f; }

        for (int tile = 0; tile < NTILES; ++tile) {
            __syncthreads();
            STORET();
            if (tile + 1 < NTILES) LOADT(tile + 1);
            __syncthreads();

            #pragma unroll
            for (int s = 0; s < 8; ++s) {
                const int l = lbase + 2 * s + half;
                ulonglong2 vp = *(const ulonglong2*)(v_s + l * KSTR + 4 * c);
                const float* mrow = m_s + l;
                #pragma unroll
                for (int q = 0; q < 8; ++q) {
                    float m = mrow[q * TK];
                    ull mm; F32X2_PACK(mm, m, m);
                    F32X2_FMA(accA[q], mm, vp.x);
                    F32X2_FMA(accB[q], mm, vp.y);
                    if (c == 0) cq[q] += m;
                }
            }
        }
        // combine l-parity halves
        #pragma unroll
        for (int q = 0; q < 8; ++q) {
            ull o;
            o = __shfl_xor_sync(0xffffffffu, accA[q], 16); F32X2_ADD(accA[q], accA[q], o);
            o = __shfl_xor_sync(0xffffffffu, accB[q], 16); F32X2_ADD(accB[q], accB[q], o);
            cq[q] += __shfl_xor_sync(0xffffffffu, cq[q], 16);
        }
        // write per-warp partials into this warp's own (dead) v_s rows
        float* pbuf = v_s + wm * 1088;
        if (half == 0) {
            #pragma unroll
            for (int q = 0; q < 8; ++q) {
                float f0, f1, f2, f3;
                F32X2_UNPACK(f0, f1, accA[q]);
                F32X2_UNPACK(f2, f3, accB[q]);
                *(float4*)(pbuf + q * ND + 4 * c) = make_float4(f0, f1, f2, f3);
            }
            if (c == 0) {
                #pragma unroll
                for (int q = 0; q < 8; ++q) pbuf[512 + q] = cq[q];
            }
        }
        asm volatile("bar.sync 1, 256;" ::: "memory");
        // reduce 8 warp-partials -> msum / cnts
        const int idx = wm * 32 + lane;   // 0..255
        #pragma unroll
        for (int r = 0; r < 2; ++r) {
            const int j = idx * 2 + r;
            float s = 0.f;
            #pragma unroll
            for (int p = 0; p < 8; ++p) s += v_s[p * 1088 + j];
            msum[j] = s;
        }
        if (idx < 8) {
            float s = 0.f;
            #pragma unroll
            for (int p = 0; p < 8; ++p) s += v_s[p * 1088 + 512 + idx];
            cnts[idx] = s;
        }
        __syncthreads();
    }

    // ================= epilogue ============================================
    if (wid < 8) {
        const int q = wid;
        float cdiv = fmaxf(cnts[q], 1.f);
        size_t orow = ((size_t)(b * NLQ + q0 + q)) * ND;
        out[orow + lane]      = msum[q * ND + lane]      / cdiv + c0;
        out[orow + lane + 32] = msum[q * ND + lane + 32] / cdiv + c1;
    }
}

extern "C" void kernel_launch(void* const* d_in, const int* in_sizes, int n_in,
                              void* d_out, int out_size) {
    const float* q    = (const float*)d_in[0];
    const float* k    = (const float*)d_in[1];
    const float* v    = (const float*)d_in[2];
    const void*  mask = d_in[3];
    float* out = (float*)d_out;

    cudaFuncSetAttribute(ga_kernel, cudaFuncAttributeMaxDynamicSharedMemorySize,
                         SMEM_BYTES);

    detect_mask_kernel<<<1, 1>>>((const unsigned int*)mask);
    ga_kernel<<<NB * (NLQ / TQ), NTHREADS, SMEM_BYTES>>>(q, k, v, mask, out);
}